// round 4
// baseline (speedup 1.0000x reference)
#include <cuda_runtime.h>
#include <math.h>
#include <stdint.h>

// Problem constants
#define BB 32
#define TT 512
#define EE 256
#define HH 256
#define GG 1024          // 4*H
#define CC 20
#define MM (BB * TT)     // 16384

// ---------------- device scratch (allocation-free rule: static __device__) --------------
__device__ float g_xp_f[(size_t)MM * GG];   // 64 MB
__device__ float g_xp_b[(size_t)MM * GG];   // 64 MB
__device__ float g_wt_f[(size_t)EE * GG];   // Whh_f^T  [e][g]
__device__ float g_wt_b[(size_t)EE * GG];   // Whh_b^T
__device__ float g_out_f[(size_t)MM * HH];  // 16 MB
__device__ float g_out_b[(size_t)MM * HH];  // 16 MB
__device__ float g_logits[(size_t)MM * CC];
__device__ float g_llh[BB];

// ---------------- kernel 1: transpose both Whh (g,e) -> (e,g) ----------------
__global__ __launch_bounds__(256)
void transpose_whh(const float* __restrict__ Wf, const float* __restrict__ Wb)
{
    int idx = blockIdx.x * blockDim.x + threadIdx.x;
    int n = GG * EE;
    if (idx < 2 * n) {
        int half = idx >= n;
        int i = idx - half * n;
        int g = i / EE, e = i % EE;
        if (half) g_wt_b[e * GG + g] = Wb[i];
        else      g_wt_f[e * GG + g] = Wf[i];
    }
}

// ---------------- kernel 2: xp = gather(emb, x[, reversed]) @ Wih^T + bias ----------------
// M=16384, N=1024, K=256. Tile 128x64, BK=16, 256 threads, 8x4 per thread.
__global__ __launch_bounds__(256)
void gemm_xp(const int* __restrict__ x, const int* __restrict__ seq_len,
             const float* __restrict__ emb, const float* __restrict__ Wih,
             const float* __restrict__ bias, int rev)
{
    const int BM = 128, BN = 64, BK = 16;
    __shared__ float As[BK * BM];
    __shared__ float Bs[BK * BN];
    __shared__ int tok[BM];

    float* __restrict__ xp = rev ? g_xp_b : g_xp_f;

    int tid = threadIdx.x;                 // 256
    int m0 = blockIdx.y * BM;
    int n0 = blockIdx.x * BN;

    if (tid < BM) {
        int m = m0 + tid;
        int b = m / TT, t = m % TT;
        int tp = t;
        if (rev) {
            int L = seq_len[b];
            if (t < L) tp = L - 1 - t;     // beyond L: x==0 -> emb row 0 == zeros
        }
        tok[tid] = x[b * TT + tp];
    }
    __syncthreads();

    float acc[8][4];
#pragma unroll
    for (int i = 0; i < 8; i++)
#pragma unroll
        for (int j = 0; j < 4; j++) acc[i][j] = 0.f;

    int ty = tid >> 4, tx = tid & 15;

    for (int k0 = 0; k0 < EE; k0 += BK) {
        // A tile: 128 rows x 16 cols = 512 float4; 2 per thread
#pragma unroll
        for (int r = 0; r < 2; r++) {
            int idx = tid * 2 + r;
            int ml = idx >> 2;
            int q = idx & 3;
            float4 v = *reinterpret_cast<const float4*>(
                &emb[(size_t)tok[ml] * EE + k0 + 4 * q]);
            As[(4 * q + 0) * BM + ml] = v.x;
            As[(4 * q + 1) * BM + ml] = v.y;
            As[(4 * q + 2) * BM + ml] = v.z;
            As[(4 * q + 3) * BM + ml] = v.w;
        }
        // B tile: 64 g-rows x 16 e-cols, store transposed Bs[e][g]
        {
            int gl = tid >> 2;
            int q = tid & 3;
            float4 v = *reinterpret_cast<const float4*>(
                &Wih[(size_t)(n0 + gl) * EE + k0 + 4 * q]);
            Bs[(4 * q + 0) * BN + gl] = v.x;
            Bs[(4 * q + 1) * BN + gl] = v.y;
            Bs[(4 * q + 2) * BN + gl] = v.z;
            Bs[(4 * q + 3) * BN + gl] = v.w;
        }
        __syncthreads();

#pragma unroll
        for (int kk = 0; kk < BK; kk++) {
            float a[8], bv[4];
            const float4* a4 = reinterpret_cast<const float4*>(&As[kk * BM + ty * 8]);
            float4 av0 = a4[0], av1 = a4[1];
            a[0] = av0.x; a[1] = av0.y; a[2] = av0.z; a[3] = av0.w;
            a[4] = av1.x; a[5] = av1.y; a[6] = av1.z; a[7] = av1.w;
            float4 bv4 = *reinterpret_cast<const float4*>(&Bs[kk * BN + tx * 4]);
            bv[0] = bv4.x; bv[1] = bv4.y; bv[2] = bv4.z; bv[3] = bv4.w;
#pragma unroll
            for (int i = 0; i < 8; i++)
#pragma unroll
                for (int j = 0; j < 4; j++) acc[i][j] += a[i] * bv[j];
        }
        __syncthreads();
    }

#pragma unroll
    for (int j = 0; j < 4; j++) {
        float bj = bias[n0 + tx * 4 + j];
#pragma unroll
        for (int i = 0; i < 8; i++) {
            xp[(size_t)(m0 + ty * 8 + i) * GG + n0 + tx * 4 + j] = acc[i][j] + bj;
        }
    }
}

// ---------------- device helper: LSTM pointwise cell update ----------------
__device__ __forceinline__ float lstm_cell(const float* __restrict__ gates,
                                           int tid, float& c)
{
    float xi = gates[tid];
    float xf = gates[HH + tid];
    float xg = gates[2 * HH + tid];
    float xo = gates[3 * HH + tid];
    float i_ = 1.f / (1.f + __expf(-xi));
    float f_ = 1.f / (1.f + __expf(-xf));
    float o_ = 1.f / (1.f + __expf(-xo));
    c = f_ * c + i_ * tanhf(xg);
    return o_ * tanhf(c);
}

// ---------------- kernel 3: LSTM scan, block per (direction, batch) ----------------
// 64 blocks x 256 threads. Thread tid owns gate columns 4tid..4tid+3 for the matvec
// and hidden unit j==tid for the cell update. Early-exit at seq_len[b].
__global__ __launch_bounds__(256)
void lstm_scan(const int* __restrict__ seq_len)
{
    int blk = blockIdx.x;
    int b = blk & 31;
    bool fwd = blk < 32;

    const float4* __restrict__ xp4 =
        reinterpret_cast<const float4*>(fwd ? g_xp_f : g_xp_b);
    const float4* __restrict__ Wt4 =
        reinterpret_cast<const float4*>(fwd ? g_wt_f : g_wt_b);
    float* __restrict__ out = fwd ? g_out_f : g_out_b;

    __shared__ float h_sm[HH];
    __shared__ float4 gate4[256];
    float* gates = reinterpret_cast<float*>(gate4);

    int tid = threadIdx.x;
    int L = seq_len[b];
    size_t base = (size_t)b * TT;

    // ---- t = 0: pure pointwise (h == 0) ----
    float c = 0.f;
    gate4[tid] = xp4[base * 256 + tid];
    __syncthreads();
    {
        float hv = lstm_cell(gates, tid, c);
        h_sm[tid] = hv;
        out[base * HH + tid] = hv;
    }
    __syncthreads();

    // ---- t = 1 .. L-1: matvec + pointwise ----
    for (int t = 1; t < L; t++) {
        size_t row = base + t;
        float4 acc = xp4[row * 256 + tid];
        const float4* h4 = reinterpret_cast<const float4*>(h_sm);
#pragma unroll 8
        for (int e4 = 0; e4 < 64; e4++) {
            float4 hv = h4[e4];
            float4 w0 = Wt4[(size_t)(4 * e4 + 0) * 256 + tid];
            float4 w1 = Wt4[(size_t)(4 * e4 + 1) * 256 + tid];
            float4 w2 = Wt4[(size_t)(4 * e4 + 2) * 256 + tid];
            float4 w3 = Wt4[(size_t)(4 * e4 + 3) * 256 + tid];
            acc.x += w0.x * hv.x + w1.x * hv.y + w2.x * hv.z + w3.x * hv.w;
            acc.y += w0.y * hv.x + w1.y * hv.y + w2.y * hv.z + w3.y * hv.w;
            acc.z += w0.z * hv.x + w1.z * hv.y + w2.z * hv.z + w3.z * hv.w;
            acc.w += w0.w * hv.x + w1.w * hv.y + w2.w * hv.z + w3.w * hv.w;
        }
        __syncthreads();          // h_sm fully consumed by all threads
        gate4[tid] = acc;
        __syncthreads();

        float hv = lstm_cell(gates, tid, c);
        h_sm[tid] = hv;
        out[row * HH + tid] = hv;
        __syncthreads();
    }
}

// ---------------- kernel 4: logits = log_softmax(concat(out_f, rev(out_b)) @ W_fc^T) ----
// One block per (b,t); skipped for t >= seq_len[b] (never read downstream).
__global__ __launch_bounds__(256)
void logits_kernel(const int* __restrict__ seq_len,
                   const float* __restrict__ W_fc)
{
    int bt = blockIdx.x;
    int b = bt / TT, t = bt % TT;
    int L = seq_len[b];
    if (t >= L) return;

    __shared__ float outs[2 * HH];
    __shared__ float dots[CC];
    __shared__ float lse_s;

    int tid = threadIdx.x;  // 256
    outs[tid]       = g_out_f[(size_t)bt * HH + tid];
    outs[HH + tid]  = g_out_b[(size_t)(b * TT + (L - 1 - t)) * HH + tid];
    __syncthreads();

    int warp = tid >> 5, lane = tid & 31;
    for (int cls = warp; cls < CC; cls += 8) {
        float acc = 0.f;
#pragma unroll 4
        for (int e = lane; e < 2 * HH; e += 32)
            acc += outs[e] * W_fc[cls * (2 * HH) + e];
#pragma unroll
        for (int off = 16; off; off >>= 1)
            acc += __shfl_down_sync(0xffffffffu, acc, off);
        if (lane == 0) dots[cls] = acc;
    }
    __syncthreads();

    if (tid == 0) {
        float m = -INFINITY;
        for (int cI = 0; cI < CC; cI++) m = fmaxf(m, dots[cI]);
        float s = 0.f;
        for (int cI = 0; cI < CC; cI++) s += expf(dots[cI] - m);
        lse_s = m + logf(s);
    }
    __syncthreads();

    if (tid < CC) g_logits[(size_t)bt * CC + tid] = dots[tid] - lse_s;
}

// ---------------- kernel 5: CRF gold score + forward algorithm, warp per batch ----------
__global__ __launch_bounds__(32)
void crf_kernel(const int* __restrict__ seq_len, const int* __restrict__ y,
                const float* __restrict__ start_t, const float* __restrict__ end_t,
                const float* __restrict__ trans)
{
    int b = blockIdx.x;
    int lane = threadIdx.x;  // 32

    __shared__ float trans_s[CC * CC];
    __shared__ float alpha_s[CC];
    for (int i = lane; i < CC * CC; i += 32) trans_s[i] = trans[i];
    __syncwarp();

    int L = seq_len[b];
    const float* lg = g_logits + (size_t)b * TT * CC;
    const int* yb = y + b * TT;

    // gold path score (parallel over t, lane-order reduce)
    float part = 0.f;
    for (int t = 1 + lane; t < L; t += 32)
        part += trans_s[yb[t - 1] * CC + yb[t]] + lg[t * CC + yb[t]];
#pragma unroll
    for (int off = 16; off; off >>= 1)
        part += __shfl_down_sync(0xffffffffu, part, off);

    float score = 0.f;
    if (lane == 0)
        score = part + start_t[yb[0]] + lg[yb[0]] + end_t[yb[L - 1]];

    // forward algorithm
    int j = lane;
    float alpha = (j < CC) ? (start_t[j] + lg[j]) : -INFINITY;
    for (int t = 1; t < L; t++) {
        if (j < CC) alpha_s[j] = alpha;
        __syncwarp();
        float na = alpha;
        if (j < CC) {
            float m = -INFINITY;
#pragma unroll
            for (int i = 0; i < CC; i++)
                m = fmaxf(m, alpha_s[i] + trans_s[i * CC + j]);
            float s = 0.f;
#pragma unroll
            for (int i = 0; i < CC; i++)
                s += expf(alpha_s[i] + trans_s[i * CC + j] - m);
            na = m + logf(s) + lg[t * CC + j];
        }
        __syncwarp();
        alpha = na;
    }

    if (j < CC) alpha_s[j] = alpha + end_t[j];
    __syncwarp();
    if (lane == 0) {
        float m = -INFINITY;
        for (int i = 0; i < CC; i++) m = fmaxf(m, alpha_s[i]);
        float s = 0.f;
        for (int i = 0; i < CC; i++) s += expf(alpha_s[i] - m);
        float logZ = m + logf(s);
        g_llh[b] = score - logZ;
    }
}

// ---------------- kernel 6: loss = -sum_b llh[b] ----------------
__global__ __launch_bounds__(32)
void finalize_kernel(float* __restrict__ out)
{
    int lane = threadIdx.x;
    float v = g_llh[lane];
#pragma unroll
    for (int off = 16; off; off >>= 1)
        v += __shfl_down_sync(0xffffffffu, v, off);
    if (lane == 0) out[0] = -v;
}

// ---------------- launch ----------------
extern "C" void kernel_launch(void* const* d_in, const int* in_sizes, int n_in,
                              void* d_out, int out_size)
{
    (void)in_sizes; (void)n_in; (void)out_size;
    const int*   x       = (const int*)  d_in[0];
    const int*   seq_len = (const int*)  d_in[1];
    const int*   y       = (const int*)  d_in[2];
    // d_in[3] = mask (derived from seq_len instead)
    const float* emb     = (const float*)d_in[4];
    const float* Wih_f   = (const float*)d_in[5];
    const float* Whh_f   = (const float*)d_in[6];
    const float* b_f     = (const float*)d_in[7];
    const float* Wih_b   = (const float*)d_in[8];
    const float* Whh_b   = (const float*)d_in[9];
    const float* b_b     = (const float*)d_in[10];
    const float* W_fc    = (const float*)d_in[11];
    const float* start_t = (const float*)d_in[12];
    const float* end_t   = (const float*)d_in[13];
    const float* trans   = (const float*)d_in[14];
    float* out = (float*)d_out;

    transpose_whh<<<(2 * GG * EE + 255) / 256, 256>>>(Whh_f, Whh_b);

    dim3 ggrid(GG / 64, MM / 128);
    gemm_xp<<<ggrid, 256>>>(x, seq_len, emb, Wih_f, b_f, 0);
    gemm_xp<<<ggrid, 256>>>(x, seq_len, emb, Wih_b, b_b, 1);

    lstm_scan<<<64, 256>>>(seq_len);

    logits_kernel<<<MM, 256>>>(seq_len, W_fc);

    crf_kernel<<<BB, 32>>>(seq_len, y, start_t, end_t, trans);

    finalize_kernel<<<1, 32>>>(out);
}

// round 5
// speedup vs baseline: 2.2648x; 2.2648x over previous
#include <cuda_runtime.h>
#include <math.h>
#include <stdint.h>

// Problem constants
#define BB 32
#define TT 512
#define EE 256
#define HH 256
#define GG 1024          // 4*H
#define CC 20
#define MM (BB * TT)     // 16384

// ---------------- device scratch (allocation-free rule: static __device__) --------------
__device__ float g_xp_f[(size_t)MM * GG];   // 64 MB
__device__ float g_xp_b[(size_t)MM * GG];   // 64 MB
__device__ float g_out_f[(size_t)MM * HH];  // 16 MB
__device__ float g_out_b[(size_t)MM * HH];  // 16 MB
__device__ float g_logits[(size_t)MM * CC];
__device__ float g_llh[BB];

// persistent-scan state
__device__ float    g_h[2][2][HH][BB];      // [dir][parity][j][b_sorted]
__device__ unsigned g_bar[2];               // per-direction arrival counter
__device__ int      g_perm[BB];             // sorted(batch) -> original batch
__device__ int      g_Lsorted[BB];          // lengths, descending
__device__ int      g_Lmax;

// ---------------- kernel 0: setup (sort batches by length desc, zero barrier/h) --------
__global__ __launch_bounds__(256)
void setup_kernel(const int* __restrict__ seq_len)
{
    int tid = threadIdx.x;
    // zero h buffers (2*2*256*32 = 32768 floats)
    for (int i = tid; i < 2 * 2 * HH * BB; i += 256)
        (&g_h[0][0][0][0])[i] = 0.f;

    if (tid == 0) {
        int L[BB], p[BB];
        for (int i = 0; i < BB; i++) { L[i] = seq_len[i]; p[i] = i; }
        // stable insertion sort, descending by L
        for (int i = 1; i < BB; i++) {
            int kl = L[i], kp = p[i];
            int j = i - 1;
            while (j >= 0 && L[j] < kl) { L[j + 1] = L[j]; p[j + 1] = p[j]; j--; }
            L[j + 1] = kl; p[j + 1] = kp;
        }
        for (int i = 0; i < BB; i++) { g_perm[i] = p[i]; g_Lsorted[i] = L[i]; }
        g_Lmax = L[0];
        g_bar[0] = 0u;
        g_bar[1] = 0u;
    }
}

// ---------------- kernel 1: xp = gather(emb, x[, reversed]) @ Wih^T + bias -------------
// M=16384, N=1024, K=256. Tile 128x128, BK=8, 256 threads, 8x8 per thread.
__global__ __launch_bounds__(256)
void gemm_xp(const int* __restrict__ x, const int* __restrict__ seq_len,
             const float* __restrict__ emb, const float* __restrict__ Wih,
             const float* __restrict__ bias, int rev)
{
    const int BM = 128, BN = 128, BK = 8;
    __shared__ float As[BK][BM];
    __shared__ float Bs[BK][BN];
    __shared__ int tok[BM];

    float* __restrict__ xp = rev ? g_xp_b : g_xp_f;

    int tid = threadIdx.x;                 // 256
    int m0 = blockIdx.y * BM;
    int n0 = blockIdx.x * BN;

    if (tid < BM) {
        int m = m0 + tid;
        int b = m / TT, t = m % TT;
        int tp = t;
        if (rev) {
            int L = seq_len[b];
            if (t < L) tp = L - 1 - t;     // beyond L: x==0 -> emb row 0 == zeros
        }
        tok[tid] = x[b * TT + tp];
    }
    __syncthreads();

    int tx = tid & 15, ty = tid >> 4;
    int am = tid >> 1, ak = (tid & 1) * 4;  // A staging: row am, k4 chunk ak
    int bn = tid >> 1, bk = (tid & 1) * 4;  // B staging

    float acc[8][8];
#pragma unroll
    for (int i = 0; i < 8; i++)
#pragma unroll
        for (int j = 0; j < 8; j++) acc[i][j] = 0.f;

    for (int k0 = 0; k0 < EE; k0 += BK) {
        float4 av = *reinterpret_cast<const float4*>(
            &emb[(size_t)tok[am] * EE + k0 + ak]);
        float4 bv = *reinterpret_cast<const float4*>(
            &Wih[(size_t)(n0 + bn) * EE + k0 + bk]);
        __syncthreads();   // previous tile fully consumed
        As[ak + 0][am] = av.x; As[ak + 1][am] = av.y;
        As[ak + 2][am] = av.z; As[ak + 3][am] = av.w;
        Bs[bk + 0][bn] = bv.x; Bs[bk + 1][bn] = bv.y;
        Bs[bk + 2][bn] = bv.z; Bs[bk + 3][bn] = bv.w;
        __syncthreads();

#pragma unroll
        for (int kk = 0; kk < BK; kk++) {
            float a[8], b[8];
            *reinterpret_cast<float4*>(&a[0]) =
                *reinterpret_cast<const float4*>(&As[kk][ty * 8]);
            *reinterpret_cast<float4*>(&a[4]) =
                *reinterpret_cast<const float4*>(&As[kk][ty * 8 + 4]);
            *reinterpret_cast<float4*>(&b[0]) =
                *reinterpret_cast<const float4*>(&Bs[kk][tx * 8]);
            *reinterpret_cast<float4*>(&b[4]) =
                *reinterpret_cast<const float4*>(&Bs[kk][tx * 8 + 4]);
#pragma unroll
            for (int i = 0; i < 8; i++)
#pragma unroll
                for (int j = 0; j < 8; j++) acc[i][j] += a[i] * b[j];
        }
    }

    // epilogue: add bias, store
    float bj[8];
#pragma unroll
    for (int j = 0; j < 8; j++) bj[j] = bias[n0 + tx * 8 + j];
#pragma unroll
    for (int i = 0; i < 8; i++) {
        size_t row = (size_t)(m0 + ty * 8 + i) * GG + n0 + tx * 8;
        float4 v0, v1;
        v0.x = acc[i][0] + bj[0]; v0.y = acc[i][1] + bj[1];
        v0.z = acc[i][2] + bj[2]; v0.w = acc[i][3] + bj[3];
        v1.x = acc[i][4] + bj[4]; v1.y = acc[i][5] + bj[5];
        v1.z = acc[i][6] + bj[6]; v1.w = acc[i][7] + bj[7];
        *reinterpret_cast<float4*>(&xp[row]) = v0;
        *reinterpret_cast<float4*>(&xp[row + 4]) = v1;
    }
}

// ---------------- kernel 2: persistent batched LSTM scan --------------------------------
// 64 CTAs total: dir = bid>>5, ci = bid&31. CTA owns hidden units j in [ci*8, ci*8+8)
// (32 gate rows). Weights for those rows live in SMEM (k-major) for the entire scan.
// Per step: tiny GEMM (32 rows x A batches x 256 k) from SMEM, cell update, h exchange
// through g_h (double-buffered) + DIY monotone-counter grid barrier per direction.
__global__ __launch_bounds__(256)
void lstm_scan2(const float* __restrict__ Whh_f, const float* __restrict__ Whh_b)
{
    extern __shared__ float sm[];
    float* Ws   = sm;                    // [256][32]  Ws[k*32 + lrow]
    float* hs   = sm + 256 * 32;         // [256][32]  hs[k*32 + b]
    float* pbuf = sm + 2 * 256 * 32;     // [4][32][32] pbuf[(s*32+r)*32 + b]
    __shared__ int perm_s[BB];
    __shared__ int Ls[BB];

    int dir = blockIdx.x >> 5;
    int ci  = blockIdx.x & 31;
    int tid = threadIdx.x;

    const float* __restrict__ xp  = dir ? g_xp_b : g_xp_f;
    const float* __restrict__ Whh = dir ? Whh_b : Whh_f;
    float* __restrict__ out       = dir ? g_out_b : g_out_f;

    if (tid < BB) { perm_s[tid] = g_perm[tid]; Ls[tid] = g_Lsorted[tid]; }
    int Lmax = g_Lmax;

    // ---- fill weight slice into SMEM, k-major: Ws[k][lrow], lrow = q*8+u ----
    for (int i = tid; i < 32 * 64; i += 256) {
        int lrow = i & 31, k4 = i >> 5;
        int q = lrow >> 3, u = lrow & 7;
        int grow = q * 256 + ci * 8 + u;
        float4 w = *reinterpret_cast<const float4*>(&Whh[(size_t)grow * 256 + k4 * 4]);
        Ws[(k4 * 4 + 0) * 32 + lrow] = w.x;
        Ws[(k4 * 4 + 1) * 32 + lrow] = w.y;
        Ws[(k4 * 4 + 2) * 32 + lrow] = w.z;
        Ws[(k4 * 4 + 3) * 32 + lrow] = w.w;
    }
    __syncthreads();

    // GEMM roles: k-slice s (64 k each), 8 row-groups x 8 batch-groups, 4x4 micro-tile
    int s    = tid >> 6;
    int s64  = tid & 63;
    int rowg = s64 & 7;
    int bg   = s64 >> 3;
    // cell roles: tid = b_cell*8 + u_cell
    int b_cell = tid >> 3;
    int u_cell = tid & 7;

    float c_state = 0.f;
    int A = BB;

    const float4* W4 = reinterpret_cast<const float4*>(Ws);  // [k][8] float4
    const float4* H4 = reinterpret_cast<const float4*>(hs);

    for (int t = 0; t < Lmax; t++) {
        while (A > 0 && Ls[A - 1] <= t) A--;
        int pw = t & 1, pr = pw ^ 1;

        // ---- fill hs from g_h[dir][pr] (contiguous 32KB copy) ----
        {
            const float4* src = reinterpret_cast<const float4*>(&g_h[dir][pr][0][0]);
            float4* dst = reinterpret_cast<float4*>(hs);
            for (int i = tid; i < 2048; i += 256) dst[i] = src[i];
        }

        // ---- prefetch this thread's xp gate values (cell role) ----
        int Lb = Ls[b_cell];
        bool act = (t < Lb);
        int ob = perm_s[b_cell];
        float xg0 = 0.f, xg1 = 0.f, xg2 = 0.f, xg3 = 0.f;
        if (act) {
            size_t xbase = ((size_t)ob * TT + t) * GG + (size_t)ci * 8 + u_cell;
            xg0 = xp[xbase];
            xg1 = xp[xbase + 256];
            xg2 = xp[xbase + 512];
            xg3 = xp[xbase + 768];
        }
        __syncthreads();   // hs ready; pbuf from previous step fully consumed

        // ---- micro-GEMM: gates[row][b] partial over k-slice s ----
        float acc[4][4];
#pragma unroll
        for (int i = 0; i < 4; i++)
#pragma unroll
            for (int j = 0; j < 4; j++) acc[i][j] = 0.f;

        if (bg * 4 < A) {
            int kbase = s * 64;
#pragma unroll 8
            for (int k = 0; k < 64; k++) {
                float4 wv = W4[(kbase + k) * 8 + rowg];
                float4 hv = H4[(kbase + k) * 8 + bg];
                acc[0][0] += wv.x * hv.x; acc[0][1] += wv.x * hv.y;
                acc[0][2] += wv.x * hv.z; acc[0][3] += wv.x * hv.w;
                acc[1][0] += wv.y * hv.x; acc[1][1] += wv.y * hv.y;
                acc[1][2] += wv.y * hv.z; acc[1][3] += wv.y * hv.w;
                acc[2][0] += wv.z * hv.x; acc[2][1] += wv.z * hv.y;
                acc[2][2] += wv.z * hv.z; acc[2][3] += wv.z * hv.w;
                acc[3][0] += wv.w * hv.x; acc[3][1] += wv.w * hv.y;
                acc[3][2] += wv.w * hv.z; acc[3][3] += wv.w * hv.w;
            }
        }
#pragma unroll
        for (int i = 0; i < 4; i++)
#pragma unroll
            for (int j = 0; j < 4; j++)
                pbuf[(s * 32 + rowg * 4 + i) * 32 + bg * 4 + j] = acc[i][j];
        __syncthreads();

        // ---- reduce 4 k-slices + cell update + write h/out ----
        if (act) {
            float g4[4];
#pragma unroll
            for (int q = 0; q < 4; q++) {
                int r = q * 8 + u_cell;
                float v = 0.f;
#pragma unroll
                for (int s2 = 0; s2 < 4; s2++)
                    v += pbuf[(s2 * 32 + r) * 32 + b_cell];
                g4[q] = v;
            }
            g4[0] += xg0; g4[1] += xg1; g4[2] += xg2; g4[3] += xg3;
            float i_ = 1.f / (1.f + __expf(-g4[0]));
            float f_ = 1.f / (1.f + __expf(-g4[1]));
            float o_ = 1.f / (1.f + __expf(-g4[3]));
            c_state = f_ * c_state + i_ * tanhf(g4[2]);
            float hv = o_ * tanhf(c_state);
            int j = ci * 8 + u_cell;
            g_h[dir][pw][j][b_cell] = hv;
            out[((size_t)ob * TT + t) * HH + j] = hv;
        }

        // ---- grid barrier (per direction), monotone counter ----
        __threadfence();
        __syncthreads();
        if (tid == 0) {
            atomicAdd(&g_bar[dir], 1u);
            unsigned tgt = 32u * (unsigned)(t + 1);
            while (*((volatile unsigned*)&g_bar[dir]) < tgt) { }
        }
        __syncthreads();
        __threadfence();
    }
}

// ---------------- kernel 3: logits = log_softmax(concat(out_f, rev(out_b)) @ W_fc^T) ---
__global__ __launch_bounds__(256)
void logits_kernel(const int* __restrict__ seq_len,
                   const float* __restrict__ W_fc)
{
    int bt = blockIdx.x;
    int b = bt / TT, t = bt % TT;
    int L = seq_len[b];
    if (t >= L) return;

    __shared__ float outs[2 * HH];
    __shared__ float dots[CC];
    __shared__ float lse_s;

    int tid = threadIdx.x;  // 256
    outs[tid]       = g_out_f[(size_t)bt * HH + tid];
    outs[HH + tid]  = g_out_b[(size_t)(b * TT + (L - 1 - t)) * HH + tid];
    __syncthreads();

    int warp = tid >> 5, lane = tid & 31;
    for (int cls = warp; cls < CC; cls += 8) {
        float acc = 0.f;
#pragma unroll 4
        for (int e = lane; e < 2 * HH; e += 32)
            acc += outs[e] * W_fc[cls * (2 * HH) + e];
#pragma unroll
        for (int off = 16; off; off >>= 1)
            acc += __shfl_down_sync(0xffffffffu, acc, off);
        if (lane == 0) dots[cls] = acc;
    }
    __syncthreads();

    if (tid == 0) {
        float m = -INFINITY;
        for (int cI = 0; cI < CC; cI++) m = fmaxf(m, dots[cI]);
        float sum = 0.f;
        for (int cI = 0; cI < CC; cI++) sum += expf(dots[cI] - m);
        lse_s = m + logf(sum);
    }
    __syncthreads();

    if (tid < CC) g_logits[(size_t)bt * CC + tid] = dots[tid] - lse_s;
}

// ---------------- kernel 4: CRF gold score + forward algorithm, warp per batch ----------
__global__ __launch_bounds__(32)
void crf_kernel(const int* __restrict__ seq_len, const int* __restrict__ y,
                const float* __restrict__ start_t, const float* __restrict__ end_t,
                const float* __restrict__ trans)
{
    int b = blockIdx.x;
    int lane = threadIdx.x;  // 32

    __shared__ float trans_s[CC * CC];
    __shared__ float alpha_s[CC];
    for (int i = lane; i < CC * CC; i += 32) trans_s[i] = trans[i];
    __syncwarp();

    int L = seq_len[b];
    const float* lg = g_logits + (size_t)b * TT * CC;
    const int* yb = y + b * TT;

    float part = 0.f;
    for (int t = 1 + lane; t < L; t += 32)
        part += trans_s[yb[t - 1] * CC + yb[t]] + lg[t * CC + yb[t]];
#pragma unroll
    for (int off = 16; off; off >>= 1)
        part += __shfl_down_sync(0xffffffffu, part, off);

    float score = 0.f;
    if (lane == 0)
        score = part + start_t[yb[0]] + lg[yb[0]] + end_t[yb[L - 1]];

    int j = lane;
    float alpha = (j < CC) ? (start_t[j] + lg[j]) : -INFINITY;
    for (int t = 1; t < L; t++) {
        if (j < CC) alpha_s[j] = alpha;
        __syncwarp();
        float na = alpha;
        if (j < CC) {
            float m = -INFINITY;
#pragma unroll
            for (int i = 0; i < CC; i++)
                m = fmaxf(m, alpha_s[i] + trans_s[i * CC + j]);
            float sum = 0.f;
#pragma unroll
            for (int i = 0; i < CC; i++)
                sum += expf(alpha_s[i] + trans_s[i * CC + j] - m);
            na = m + logf(sum) + lg[t * CC + j];
        }
        __syncwarp();
        alpha = na;
    }

    if (j < CC) alpha_s[j] = alpha + end_t[j];
    __syncwarp();
    if (lane == 0) {
        float m = -INFINITY;
        for (int i = 0; i < CC; i++) m = fmaxf(m, alpha_s[i]);
        float sum = 0.f;
        for (int i = 0; i < CC; i++) sum += expf(alpha_s[i] - m);
        float logZ = m + logf(sum);
        g_llh[b] = score - logZ;
    }
}

// ---------------- kernel 5: loss = -sum_b llh[b] ----------------
__global__ __launch_bounds__(32)
void finalize_kernel(float* __restrict__ out)
{
    int lane = threadIdx.x;
    float v = g_llh[lane];
#pragma unroll
    for (int off = 16; off; off >>= 1)
        v += __shfl_down_sync(0xffffffffu, v, off);
    if (lane == 0) out[0] = -v;
}

// ---------------- launch ----------------
extern "C" void kernel_launch(void* const* d_in, const int* in_sizes, int n_in,
                              void* d_out, int out_size)
{
    (void)in_sizes; (void)n_in; (void)out_size;
    const int*   x       = (const int*)  d_in[0];
    const int*   seq_len = (const int*)  d_in[1];
    const int*   y       = (const int*)  d_in[2];
    // d_in[3] = mask (derived from seq_len instead)
    const float* emb     = (const float*)d_in[4];
    const float* Wih_f   = (const float*)d_in[5];
    const float* Whh_f   = (const float*)d_in[6];
    const float* b_f     = (const float*)d_in[7];
    const float* Wih_b   = (const float*)d_in[8];
    const float* Whh_b   = (const float*)d_in[9];
    const float* b_b     = (const float*)d_in[10];
    const float* W_fc    = (const float*)d_in[11];
    const float* start_t = (const float*)d_in[12];
    const float* end_t   = (const float*)d_in[13];
    const float* trans   = (const float*)d_in[14];
    float* out = (float*)d_out;

    // scan dynamic SMEM: Ws 32KB + hs 32KB + pbuf 16KB = 80KB
    const int scan_smem = (2 * 256 * 32 + 4 * 32 * 32) * (int)sizeof(float);
    static int smem_set = 0;
    if (!smem_set) {
        cudaFuncSetAttribute(lstm_scan2,
                             cudaFuncAttributeMaxDynamicSharedMemorySize, scan_smem);
        smem_set = 1;
    }

    setup_kernel<<<1, 256>>>(seq_len);

    dim3 ggrid(GG / 128, MM / 128);
    gemm_xp<<<ggrid, 256>>>(x, seq_len, emb, Wih_f, b_f, 0);
    gemm_xp<<<ggrid, 256>>>(x, seq_len, emb, Wih_b, b_b, 1);

    lstm_scan2<<<64, 256, scan_smem>>>(Whh_f, Whh_b);

    logits_kernel<<<MM, 256>>>(seq_len, W_fc);

    crf_kernel<<<BB, 32>>>(seq_len, y, start_t, end_t, trans);

    finalize_kernel<<<1, 32>>>(out);
}